// round 3
// baseline (speedup 1.0000x reference)
#include <cuda_runtime.h>
#include <cstdint>

// ---------------------------------------------------------------------------
// Problem constants
// ---------------------------------------------------------------------------
#define NN 50000
#define EE 800000
#define IN_CH 128
#define HID 64
#define HEADS 4
#define HC (HEADS * HID)   // 256
#define NREL 3
#define WIDE (NREL * HC)   // 768
#define OUT_CH 64

// ---------------------------------------------------------------------------
// Scratch (device globals; no allocation allowed anywhere)
// ---------------------------------------------------------------------------
__device__ __align__(16) float g_h[(size_t)NN * WIDE];     // all-relation GEMM output
__device__ __align__(16) float g_out1[(size_t)NN * HC];    // layer1 accumulation
__device__ __align__(16) float g_out2[(size_t)NN * HID];   // layer2 accumulation
__device__ __align__(16) float g_als[(size_t)NREL * NN * HEADS];
__device__ __align__(16) float g_ald[(size_t)NREL * NN * HEADS];
__device__ __align__(16) float g_denom[(size_t)NREL * NN * HEADS];

// ---------------------------------------------------------------------------
// Helpers
// ---------------------------------------------------------------------------
__device__ __forceinline__ float lrelu(float x) { return fmaxf(x, 0.2f * x); }

__device__ __forceinline__ void red_add_v4(float* p, float4 v) {
    asm volatile("red.global.add.v4.f32 [%0], {%1, %2, %3, %4};"
                 :: "l"(p), "f"(v.x), "f"(v.y), "f"(v.z), "f"(v.w) : "memory");
}
__device__ __forceinline__ void red_add_v2(float* p, float2 v) {
    asm volatile("red.global.add.v2.f32 [%0], {%1, %2};"
                 :: "l"(p), "f"(v.x), "f"(v.y) : "memory");
}

// ---------------------------------------------------------------------------
// Register-prefetch pipelined SGEMM.
//   C[M, Ntot] = op(A)[M,K] @ Wgrouped (+ bias),  Ntot = gridDim.x * BN
// W is a stack of NREL weight matrices of shape [K, GN]; block_col selects the
// plane: grp = block_col / GN. For ungrouped GEMMs pass GN = Ntot (grp = 0).
// ASEL: -1 = A from param, 1 = g_out1, 2 = g_out2. CSEL: -1 = param, 0 = g_h.
// ---------------------------------------------------------------------------
template<int BM, int BN, int BK, int TM, int TN, bool RELU_A, bool BIAS,
         int ASEL, int CSEL>
__global__ void __launch_bounds__((BM / TM) * (BN / TN))
sgemm_kernel(const float* __restrict__ Ap, const float* __restrict__ W,
             float* __restrict__ Cp, const float* __restrict__ bias,
             int M, int K, int GN, int ldc) {
    constexpr int NT = (BM / TM) * (BN / TN);
    constexpr int LA = BM * BK / (4 * NT);
    constexpr int LB = BK * BN / (4 * NT);
    constexpr int BMP = BM + 4;
    __shared__ float As[BK][BMP];
    __shared__ float Bs[BK][BN];

    const float* A = (ASEL == 1) ? (const float*)g_out1
                   : (ASEL == 2) ? (const float*)g_out2 : Ap;
    float* C = (CSEL == 0) ? (float*)g_h : Cp;

    const int tid = threadIdx.x;
    const int block_row = blockIdx.y * BM;
    const int block_col = blockIdx.x * BN;
    const int grp = block_col / GN;
    const float* B = W + (size_t)grp * K * GN + (block_col - grp * GN);
    const int tcol = tid % (BN / TN);
    const int trow = tid / (BN / TN);

    float4 aR[LA], bR[LB];

    // prologue: load tile 0 into registers
#pragma unroll
    for (int j = 0; j < LA; j++) {
        int i = tid + j * NT;
        int r = i / (BK / 4), c4 = i % (BK / 4);
        int gr = block_row + r;
        float4 v = make_float4(0.f, 0.f, 0.f, 0.f);
        if (gr < M) v = *(const float4*)(A + (size_t)gr * K + c4 * 4);
        if (RELU_A) {
            v.x = fmaxf(v.x, 0.f); v.y = fmaxf(v.y, 0.f);
            v.z = fmaxf(v.z, 0.f); v.w = fmaxf(v.w, 0.f);
        }
        aR[j] = v;
    }
#pragma unroll
    for (int j = 0; j < LB; j++) {
        int i = tid + j * NT;
        int r = i / (BN / 4), c4 = i % (BN / 4);
        bR[j] = *(const float4*)(B + (size_t)r * GN + c4 * 4);
    }

    float acc[TM][TN];
#pragma unroll
    for (int i = 0; i < TM; i++)
#pragma unroll
        for (int j = 0; j < TN; j++) acc[i][j] = 0.f;

    const int nk = K / BK;
    for (int t = 0; t < nk; t++) {
        // commit prefetched registers to shared
#pragma unroll
        for (int j = 0; j < LA; j++) {
            int i = tid + j * NT;
            int r = i / (BK / 4), c4 = i % (BK / 4);
            As[c4 * 4 + 0][r] = aR[j].x; As[c4 * 4 + 1][r] = aR[j].y;
            As[c4 * 4 + 2][r] = aR[j].z; As[c4 * 4 + 3][r] = aR[j].w;
        }
#pragma unroll
        for (int j = 0; j < LB; j++) {
            int i = tid + j * NT;
            int r = i / (BN / 4), c4 = i % (BN / 4);
            *(float4*)&Bs[r][c4 * 4] = bR[j];
        }
        __syncthreads();

        // prefetch next tile (LDGs overlap the FFMA block below)
        if (t + 1 < nk) {
            int k0 = (t + 1) * BK;
#pragma unroll
            for (int j = 0; j < LA; j++) {
                int i = tid + j * NT;
                int r = i / (BK / 4), c4 = i % (BK / 4);
                int gr = block_row + r;
                float4 v = make_float4(0.f, 0.f, 0.f, 0.f);
                if (gr < M) v = *(const float4*)(A + (size_t)gr * K + k0 + c4 * 4);
                if (RELU_A) {
                    v.x = fmaxf(v.x, 0.f); v.y = fmaxf(v.y, 0.f);
                    v.z = fmaxf(v.z, 0.f); v.w = fmaxf(v.w, 0.f);
                }
                aR[j] = v;
            }
#pragma unroll
            for (int j = 0; j < LB; j++) {
                int i = tid + j * NT;
                int r = i / (BN / 4), c4 = i % (BN / 4);
                bR[j] = *(const float4*)(B + (size_t)(k0 + r) * GN + c4 * 4);
            }
        }

#pragma unroll
        for (int kk = 0; kk < BK; kk++) {
            float ar[TM], br[TN];
#pragma unroll
            for (int i = 0; i < TM; i += 4)
                *(float4*)&ar[i] = *(const float4*)&As[kk][trow * TM + i];
#pragma unroll
            for (int j = 0; j < TN; j += 4)
                *(float4*)&br[j] = *(const float4*)&Bs[kk][tcol * TN + j];
#pragma unroll
            for (int i = 0; i < TM; i++)
#pragma unroll
                for (int j = 0; j < TN; j++) acc[i][j] += ar[i] * br[j];
        }
        __syncthreads();
    }

#pragma unroll
    for (int i = 0; i < TM; i++) {
        int gr = block_row + trow * TM + i;
        if (gr >= M) continue;
#pragma unroll
        for (int j = 0; j < TN; j += 4) {
            int gc = block_col + tcol * TN + j;
            float4 v = make_float4(acc[i][j], acc[i][j + 1], acc[i][j + 2], acc[i][j + 3]);
            if (BIAS) {
                v.x += bias[gc]; v.y += bias[gc + 1];
                v.z += bias[gc + 2]; v.w += bias[gc + 3];
            }
            *(float4*)(C + (size_t)gr * ldc + gc) = v;
        }
    }
}

// ---------------------------------------------------------------------------
// Attention coefficients for ALL relations.
// One warp per (relation, node); 8 lanes per head, 8 channels per lane.
// Reads the wide g_h ([N, 768], relation plane r at col r*256).
// Also zeroes g_denom (replaces a memset node).
// ---------------------------------------------------------------------------
__global__ void attn_coef_all(const float* __restrict__ as_base,
                              const float* __restrict__ ad_base, int N) {
    int w = (blockIdx.x * blockDim.x + threadIdx.x) >> 5;
    int lane = threadIdx.x & 31;
    if (w >= NREL * N) return;
    int r = w / N;
    int node = w - r * N;
    int head = lane >> 3;
    int coff = head * HID + (lane & 7) * 8;
    const float4* hp = (const float4*)(g_h + (size_t)node * WIDE + r * HC + coff);
    const float4* sp = (const float4*)(as_base + r * HC + coff);
    const float4* dp = (const float4*)(ad_base + r * HC + coff);
    float4 h0 = hp[0], h1 = hp[1];
    float4 s0 = sp[0], s1 = sp[1];
    float4 d0 = dp[0], d1 = dp[1];
    float ps = h0.x * s0.x + h0.y * s0.y + h0.z * s0.z + h0.w * s0.w
             + h1.x * s1.x + h1.y * s1.y + h1.z * s1.z + h1.w * s1.w;
    float pd = h0.x * d0.x + h0.y * d0.y + h0.z * d0.z + h0.w * d0.w
             + h1.x * d1.x + h1.y * d1.y + h1.z * d1.z + h1.w * d1.w;
#pragma unroll
    for (int off = 4; off; off >>= 1) {
        ps += __shfl_down_sync(0xffffffffu, ps, off);
        pd += __shfl_down_sync(0xffffffffu, pd, off);
    }
    if ((lane & 7) == 0) {
        size_t idx = ((size_t)r * N + node) * HEADS + head;
        g_als[idx] = ps;
        g_ald[idx] = pd;
        g_denom[idx] = 0.f;
    }
}

// ---------------------------------------------------------------------------
// Work-item decode shared by the edge kernels.
// Virtual index space: [0, 3*(E+N)); relation r = idx/(E+N); within a relation,
// e < E are real edges, e >= E are self-loops (skipped for r==0).
// ---------------------------------------------------------------------------
__device__ __forceinline__ bool decode_edge(int idx, int E, int N,
                                            const int* e0, const int* e1, const int* e2,
                                            int& r, int& s, int& d) {
    int EN = E + N;
    r = idx / EN;
    int e = idx - r * EN;
    if (e < E) {
        const int* ep = (r == 0) ? e0 : (r == 1) ? e1 : e2;
        s = ep[e];
        d = ep[E + e];
    } else {
        if (r == 0) return false;   // 'blocks' has no self-loops
        s = d = e - E;
    }
    return true;
}

// ---------------------------------------------------------------------------
// Pass A: softmax denominators (all relations). One thread per work item.
// Shift-free softmax: logits are O(1) here, exp cannot overflow, and
// alpha = exp(l)/sum(exp(l)) is invariant to the max-shift in the reference.
// ---------------------------------------------------------------------------
__global__ void passA_all(const int* __restrict__ e0, const int* __restrict__ e1,
                          const int* __restrict__ e2, int E, int N) {
    int idx = blockIdx.x * blockDim.x + threadIdx.x;
    if (idx >= NREL * (E + N)) return;
    int r, s, d;
    if (!decode_edge(idx, E, N, e0, e1, e2, r, s, d)) return;
    const float* als = g_als + (size_t)r * N * HEADS;
    const float* ald = g_ald + (size_t)r * N * HEADS;
    float* denom = g_denom + (size_t)r * N * HEADS;
    float4 as4 = *(const float4*)(als + (size_t)s * 4);
    float4 ad4 = *(const float4*)(ald + (size_t)d * 4);
    float4 ex;
    ex.x = __expf(lrelu(as4.x + ad4.x));
    ex.y = __expf(lrelu(as4.y + ad4.y));
    ex.z = __expf(lrelu(as4.z + ad4.z));
    ex.w = __expf(lrelu(as4.w + ad4.w));
    red_add_v4(denom + (size_t)d * 4, ex);
}

// ---------------------------------------------------------------------------
// Pass B layer1 (concat): one warp per work item; lane covers 8 of 256 ch.
// g_out1[dst, h, c] += alpha[h] * g_h[src, r*256 + h*64 + c]
// ---------------------------------------------------------------------------
__global__ void passB1_all(const int* __restrict__ e0, const int* __restrict__ e1,
                           const int* __restrict__ e2, int E, int N) {
    int gt = blockIdx.x * blockDim.x + threadIdx.x;
    int idx = gt >> 5, lane = gt & 31;
    if (idx >= NREL * (E + N)) return;
    int r, s, d;
    if (!decode_edge(idx, E, N, e0, e1, e2, r, s, d)) return;
    size_t plane = (size_t)r * N * HEADS;
    int head = lane >> 3;
    float as_ = g_als[plane + (size_t)s * 4 + head];
    float ad_ = g_ald[plane + (size_t)d * 4 + head];
    float dn  = g_denom[plane + (size_t)d * 4 + head];
    float alpha = __expf(lrelu(as_ + ad_)) / (dn + 1e-16f);
    const float4* hp = (const float4*)(g_h + (size_t)s * WIDE + r * HC) + lane * 2;
    float4 v0 = hp[0], v1 = hp[1];
    v0.x *= alpha; v0.y *= alpha; v0.z *= alpha; v0.w *= alpha;
    v1.x *= alpha; v1.y *= alpha; v1.z *= alpha; v1.w *= alpha;
    float* op = g_out1 + (size_t)d * HC + lane * 8;
    red_add_v4(op, v0);
    red_add_v4(op + 4, v1);
}

// ---------------------------------------------------------------------------
// Pass B layer2 (mean over heads): one warp per work item; lane covers 2 of 64.
// g_out2[dst, c] += 0.25 * sum_h alpha[h] * g_h[src, r*256 + h*64 + c]
// ---------------------------------------------------------------------------
__global__ void passB2_all(const int* __restrict__ e0, const int* __restrict__ e1,
                           const int* __restrict__ e2, int E, int N) {
    int gt = blockIdx.x * blockDim.x + threadIdx.x;
    int idx = gt >> 5, lane = gt & 31;
    if (idx >= NREL * (E + N)) return;
    int r, s, d;
    if (!decode_edge(idx, E, N, e0, e1, e2, r, s, d)) return;
    size_t plane = (size_t)r * N * HEADS;
    float4 as4 = *(const float4*)(g_als + plane + (size_t)s * 4);
    float4 ad4 = *(const float4*)(g_ald + plane + (size_t)d * 4);
    float4 dn4 = *(const float4*)(g_denom + plane + (size_t)d * 4);
    float al[4];
    al[0] = 0.25f * __expf(lrelu(as4.x + ad4.x)) / (dn4.x + 1e-16f);
    al[1] = 0.25f * __expf(lrelu(as4.y + ad4.y)) / (dn4.y + 1e-16f);
    al[2] = 0.25f * __expf(lrelu(as4.z + ad4.z)) / (dn4.z + 1e-16f);
    al[3] = 0.25f * __expf(lrelu(as4.w + ad4.w)) / (dn4.w + 1e-16f);
    const float* hrow = g_h + (size_t)s * WIDE + r * HC;
    float2 acc = make_float2(0.f, 0.f);
#pragma unroll
    for (int hd = 0; hd < 4; hd++) {
        float2 v = *(const float2*)(hrow + hd * HID + lane * 2);
        acc.x += al[hd] * v.x;
        acc.y += al[hd] * v.y;
    }
    red_add_v2(g_out2 + (size_t)d * HID + lane * 2, acc);
}

// ---------------------------------------------------------------------------
// Init accumulation buffers with summed biases (3 relations contribute b each).
// SEL: 1 = g_out1 (C=HC), 2 = g_out2 (C=HID)
// ---------------------------------------------------------------------------
template<int SEL, int C>
__global__ void init_out_kernel(const float* __restrict__ b, int total) {
    int i = blockIdx.x * blockDim.x + threadIdx.x;
    if (i >= total) return;
    int c = i % C;
    float v = b[c] + b[C + c] + b[2 * C + c];
    if (SEL == 1) g_out1[i] = v; else g_out2[i] = v;
}

// ---------------------------------------------------------------------------
// Launcher: kernel launches ONLY (graph-capture safe)
// ---------------------------------------------------------------------------
extern "C" void kernel_launch(void* const* d_in, const int* in_sizes, int n_in,
                              void* d_out, int out_size) {
    const float* x   = (const float*)d_in[0];
    const int*   e0  = (const int*)d_in[1];
    const int*   e1  = (const int*)d_in[2];
    const int*   e2  = (const int*)d_in[3];
    const float* W1  = (const float*)d_in[4];
    const float* a1s = (const float*)d_in[5];
    const float* a1d = (const float*)d_in[6];
    const float* b1  = (const float*)d_in[7];
    const float* W2  = (const float*)d_in[8];
    const float* a2s = (const float*)d_in[9];
    const float* a2d = (const float*)d_in[10];
    const float* b2  = (const float*)d_in[11];
    const float* Wl  = (const float*)d_in[12];
    const float* bl  = (const float*)d_in[13];
    float* out = (float*)d_out;

    const int N = in_sizes[0] / IN_CH;
    const int E = in_sizes[1] / 2;
    const int nwork = NREL * (E + N);

    // ---------------- Layer 1 (concat) ----------------
    init_out_kernel<1, HC><<<(N * HC + 255) / 256, 256>>>(b1, N * HC);
    {   // g_h[:, r*256:(r+1)*256] = x @ W1[r], all r at once
        dim3 grid(WIDE / 128, (N + 127) / 128);
        sgemm_kernel<128, 128, 16, 8, 8, false, false, -1, 0><<<grid, 256>>>(
            x, W1, nullptr, nullptr, N, IN_CH, HC, WIDE);
    }
    attn_coef_all<<<(NREL * N * 32 + 255) / 256, 256>>>(a1s, a1d, N);
    passA_all<<<(nwork + 255) / 256, 256>>>(e0, e1, e2, E, N);
    {
        long long th = (long long)nwork * 32;
        passB1_all<<<(unsigned)((th + 255) / 256), 256>>>(e0, e1, e2, E, N);
    }

    // ---------------- Layer 2 (mean over heads) ----------------
    init_out_kernel<2, HID><<<(N * HID + 255) / 256, 256>>>(b2, N * HID);
    {   // g_h[:, r*256:(r+1)*256] = relu(g_out1) @ W2[r]
        dim3 grid(WIDE / 128, (N + 127) / 128);
        sgemm_kernel<128, 128, 16, 8, 8, true, false, 1, 0><<<grid, 256>>>(
            nullptr, W2, nullptr, nullptr, N, HC, HC, WIDE);
    }
    attn_coef_all<<<(NREL * N * 32 + 255) / 256, 256>>>(a2s, a2d, N);
    passA_all<<<(nwork + 255) / 256, 256>>>(e0, e1, e2, E, N);
    {
        long long th = (long long)nwork * 32;
        passB2_all<<<(unsigned)((th + 255) / 256), 256>>>(e0, e1, e2, E, N);
    }

    // ---------------- Final linear: out = relu(g_out2) @ Wl + bl ----------------
    {
        dim3 grid(1, (N + 127) / 128);
        sgemm_kernel<128, 64, 16, 4, 8, true, true, 2, -1><<<grid, 256>>>(
            nullptr, Wl, out, bl, N, OUT_CH, OUT_CH, OUT_CH);
    }
}